// round 14
// baseline (speedup 1.0000x reference)
#include <cuda_runtime.h>
#include <cuda_fp16.h>
#include <cstdint>

#define NB  4
#define NS  2048
#define ND  512
#define NH  8
#define NDH 64

// ---------------------------------------------------------------------------
// Scratch (device globals: allocation-free rule)
// ---------------------------------------------------------------------------
__device__ __half g_qh[NB * NH * NS * NDH];   // hi only (pre-scaled)
__device__ __half g_kh[NB * NH * NS * NDH];   // hi only
__device__ __half g_vh[NB * NH * NS * NDH];   // hi only
__device__ __half g_ch[NB * NS * ND];         // ctx hi only
__device__ __half g_ah[3][NB * NS * ND];      // Q/K/V activation hi
__device__ __half g_wh[4][ND * ND];           // Wq,Wk,Wv,Wo hi
__device__ int    g_ctr;                      // attn work-stealing counter

// ---------------------------------------------------------------------------
__device__ __forceinline__ uint32_t smem_u32(const void* p) {
    uint32_t a;
    asm("{ .reg .u64 t; cvta.to.shared.u64 t, %1; cvt.u32.u64 %0, t; }"
        : "=r"(a) : "l"(p));
    return a;
}
__device__ __forceinline__ void cp_async16(uint32_t dst, const void* src) {
    asm volatile("cp.async.ca.shared.global [%0], [%1], 16;"
                 :: "r"(dst), "l"(src) : "memory");
}
__device__ __forceinline__ void cp_commit() {
    asm volatile("cp.async.commit_group;" ::: "memory");
}
__device__ __forceinline__ void ldsm_x4(uint32_t addr, uint32_t& r0, uint32_t& r1,
                                        uint32_t& r2, uint32_t& r3) {
    asm volatile("ldmatrix.sync.aligned.m8n8.x4.shared.b16 {%0,%1,%2,%3}, [%4];"
                 : "=r"(r0), "=r"(r1), "=r"(r2), "=r"(r3) : "r"(addr));
}
__device__ __forceinline__ void ldsm_x4_t(uint32_t addr, uint32_t& r0, uint32_t& r1,
                                          uint32_t& r2, uint32_t& r3) {
    asm volatile("ldmatrix.sync.aligned.m8n8.x4.trans.shared.b16 {%0,%1,%2,%3}, [%4];"
                 : "=r"(r0), "=r"(r1), "=r"(r2), "=r"(r3) : "r"(addr));
}
__device__ __forceinline__ void mma16816(float* c, const uint32_t* a, const uint32_t* b) {
    asm volatile(
        "mma.sync.aligned.m16n8k16.row.col.f32.f16.f16.f32 "
        "{%0,%1,%2,%3}, {%4,%5,%6,%7}, {%8,%9}, {%0,%1,%2,%3};"
        : "+f"(c[0]), "+f"(c[1]), "+f"(c[2]), "+f"(c[3])
        : "r"(a[0]), "r"(a[1]), "r"(a[2]), "r"(a[3]), "r"(b[0]), "r"(b[1]));
}
__device__ __forceinline__ float ex2(float x) {
    float y;
    asm("ex2.approx.ftz.f32 %0, %1;" : "=f"(y) : "f"(x));
    return y;
}
__device__ __forceinline__ uint32_t pack_h2(float a, float b) {
    __half2 t = __floats2half2_rn(a, b);
    return *(uint32_t*)&t;
}

// ---------------------------------------------------------------------------
// Merged conversions (fp32 -> fp16 hi), 2 x float4 per thread
// ---------------------------------------------------------------------------
__device__ __forceinline__ void conv8(const float* in, __half* hi, int idx, int n4) {
#pragma unroll
    for (int j = 0; j < 2; ++j) {
        int i = idx + j;
        if (i < n4) {
            float4 v = ((const float4*)in)[i];
            __half h[4] = {__float2half_rn(v.x), __float2half_rn(v.y),
                           __float2half_rn(v.z), __float2half_rn(v.w)};
            ((uint2*)hi)[i] = *(uint2*)h;
        }
    }
}

__global__ __launch_bounds__(256) void conv_w4(
    const float* w0, const float* w1, const float* w2, const float* w3,
    __half* h0, __half* h1, __half* h2, __half* h3, int n4)
{
    const float* in; __half* hi;
    switch (blockIdx.y) {
        case 0:  in = w0; hi = h0; break;
        case 1:  in = w1; hi = h1; break;
        case 2:  in = w2; hi = h2; break;
        default: in = w3; hi = h3; break;
    }
    conv8(in, hi, (blockIdx.x * 256 + threadIdx.x) * 2, n4);
}

__global__ __launch_bounds__(256) void conv_a3(
    const float* a0, const float* a1, const float* a2,
    __half* h0, __half* h1, __half* h2, int n4)
{
    // reset the attention work-stealing counter (stream-ordered before attn)
    if (blockIdx.x == 0 && blockIdx.y == 0 && threadIdx.x == 0) g_ctr = 0;
    const float* in; __half* hi;
    switch (blockIdx.y) {
        case 0:  in = a0; hi = h0; break;
        case 1:  in = a1; hi = h1; break;
        default: in = a2; hi = h2; break;
    }
    conv8(in, hi, (blockIdx.x * 256 + threadIdx.x) * 2, n4);
}

// ---------------------------------------------------------------------------
// HMMA projection GEMM body (R12-proven): C[8192,512] = X @ W^T + bias
// 256 threads, 8 warps (4m x 2n), warp tile 32x64, BK=64, double-buffered.
// MODE 0: fp32 row-major out. MODE 1: fp16 hi out, head layout, scaled.
// ---------------------------------------------------------------------------
#define ROWB   144           // 64 halves (128B) + 16B pad
#define ARRSZ  (128 * ROWB)  // 18432
#define STG    (2 * ARRSZ)
#define PROJ_SMEM (2 * STG)  // 73728

template <int MODE>
__device__ __forceinline__ void proj_body(
    const __half* __restrict__ Ah, const __half* __restrict__ Bh,
    const float* __restrict__ bias, float* __restrict__ outF,
    __half* __restrict__ outH, float scale, char* smem)
{
    const uint32_t sb = smem_u32(smem);
    const int tid  = threadIdx.x;
    const int lane = tid & 31;
    const int wid  = tid >> 5;
    const int warp_m = wid & 3;
    const int warp_n = wid >> 2;
    const int m0 = blockIdx.x * 128;
    const int n0 = blockIdx.y * 128;

    const uint32_t a_off = (uint32_t)((warp_m * 32 + (lane & 15)) * ROWB + (lane >> 4) * 16);
    const uint32_t b_off = (uint32_t)((warp_n * 64 + (lane & 7) + 8 * (lane >> 4)) * ROWB
                                      + ((lane >> 3) & 1) * 16);

    float acc[2][8][4];
#pragma unroll
    for (int mi = 0; mi < 2; ++mi)
#pragma unroll
        for (int ni = 0; ni < 8; ++ni)
#pragma unroll
            for (int q = 0; q < 4; ++q) acc[mi][ni][q] = 0.0f;

    auto load_chunk = [&](int c, int stage) {
        const int k0 = c * 64;
        const uint32_t st = sb + stage * STG;
#pragma unroll
        for (int i = 0; i < 4; ++i) {
            const int c2 = tid + i * 256;
            const int r  = c2 >> 3;
            const int g  = c2 & 7;
            cp_async16(st + r * ROWB + g * 16,
                       Ah + (m0 + r) * ND + k0 + g * 8);
            cp_async16(st + ARRSZ + r * ROWB + g * 16,
                       Bh + (n0 + r) * ND + k0 + g * 8);
        }
        cp_commit();
    };

    load_chunk(0, 0);

    for (int c = 0; c < 8; ++c) {
        const int stage = c & 1;
        if (c < 7) {
            load_chunk(c + 1, stage ^ 1);
            asm volatile("cp.async.wait_group 1;" ::: "memory");
        } else {
            asm volatile("cp.async.wait_group 0;" ::: "memory");
        }
        __syncthreads();

        const uint32_t st = sb + stage * STG;
#pragma unroll
        for (int ks = 0; ks < 4; ++ks) {
            const uint32_t kb = ks * 32;
            uint32_t ah[2][4];
#pragma unroll
            for (int mi = 0; mi < 2; ++mi) {
                uint32_t adr = st + a_off + mi * (16 * ROWB) + kb;
                ldsm_x4(adr, ah[mi][0], ah[mi][1], ah[mi][2], ah[mi][3]);
            }
#pragma unroll
            for (int nb = 0; nb < 4; ++nb) {
                uint32_t adr = st + ARRSZ + b_off + nb * (16 * ROWB) + kb;
                uint32_t t0, t1, t2, t3;
                ldsm_x4(adr, t0, t1, t2, t3);
                uint32_t bhA[2] = {t0, t1}, bhB[2] = {t2, t3};
#pragma unroll
                for (int mi = 0; mi < 2; ++mi) {
                    mma16816(acc[mi][nb*2],   ah[mi], bhA);
                    mma16816(acc[mi][nb*2+1], ah[mi], bhB);
                }
            }
        }
        __syncthreads();
    }

    const int crow = lane >> 2;
    const int ccol = (lane & 3) * 2;
#pragma unroll
    for (int mi = 0; mi < 2; ++mi) {
#pragma unroll
        for (int half = 0; half < 2; ++half) {
            const int m = m0 + warp_m * 32 + mi * 16 + crow + half * 8;
            const int b = m >> 11, s = m & 2047;
#pragma unroll
            for (int ni = 0; ni < 8; ++ni) {
                const int n = n0 + warp_n * 64 + ni * 8 + ccol;
                float v0 = acc[mi][ni][half * 2 + 0] + bias[n];
                float v1 = acc[mi][ni][half * 2 + 1] + bias[n + 1];
                if (MODE == 1) {
                    v0 *= scale; v1 *= scale;
                    const int head = n >> 6, d = n & 63;
                    const int idx = ((b * NH + head) * NS + s) * NDH + d;
                    *(uint32_t*)&outH[idx] = pack_h2(v0, v1);
                } else {
                    *(float2*)&outF[m * ND + n] = make_float2(v0, v1);
                }
            }
        }
    }
}

// Fused Q/K/V projections, persistent z-loop: grid (64,4), one wave.
__global__ __launch_bounds__(256, 2) void proj_qkv(
    const __half* AhQ, const __half* BhQ, const float* biasQ, __half* outQ, float scaleQ,
    const __half* AhK, const __half* BhK, const float* biasK, __half* outK,
    const __half* AhV, const __half* BhV, const float* biasV, __half* outV)
{
    extern __shared__ char smem[];
#pragma unroll 1
    for (int z = 0; z < 3; ++z) {
        const __half *Ah, *Bh; const float* bias; __half* outH; float scale;
        if (z == 0)      { Ah = AhQ; Bh = BhQ; bias = biasQ; outH = outQ; scale = scaleQ; }
        else if (z == 1) { Ah = AhK; Bh = BhK; bias = biasK; outH = outK; scale = 1.0f; }
        else             { Ah = AhV; Bh = BhV; bias = biasV; outH = outV; scale = 1.0f; }
        proj_body<1>(Ah, Bh, bias, nullptr, outH, scale, smem);
        __syncthreads();
    }
}

// Output projection, fp32 out
__global__ __launch_bounds__(256, 2) void proj_o(
    const __half* Ah, const __half* Bh, const float* bias, float* outF)
{
    extern __shared__ char smem[];
    proj_body<0>(Ah, Bh, bias, outF, nullptr, 1.0f, smem);
}

// ---------------------------------------------------------------------------
// HMMA flash attention, PERSISTENT work-stealing. 296 CTAs x 256 thr, 2/SM.
// Work item w in [0,512): bh = w & 31 (fast-varying: mixes batches),
// q-tile = w >> 5. Per item: 128 q rows, KV tile 64, 3-stage pipeline.
// q/k/v/P/ctx fp16 hi; log2-domain softmax; mask on last KV tile only.
// ---------------------------------------------------------------------------
#define QROWB 144
#define QARR  18432
#define KARRA 9216
#define KVSTG (2 * KARRA)
#define ATTN_SMEM (QARR + 3 * KVSTG)      // 73728
#define NITEMS 512

__global__ __launch_bounds__(256, 2) void attn_hmma(
    const __half* __restrict__ qh,
    const __half* __restrict__ kh, const __half* __restrict__ vh,
    __half* __restrict__ ch,
    const void* __restrict__ masked_raw)
{
    extern __shared__ char smem[];
    __shared__ int s_item;
    const uint32_t sb = smem_u32(smem);
    const int tid  = threadIdx.x;
    const int lane = tid & 31;
    const int wid  = tid >> 5;

    for (;;) {
        if (tid == 0) s_item = atomicAdd(&g_ctr, 1);
        __syncthreads();                   // publish item; protect smem reuse
        const int w = s_item;
        if (w >= NITEMS) break;

        const int bh = w & 31;
        const int b  = bh >> 3;
        const int h  = bh & 7;
        const int q0 = (w >> 5) << 7;
        const int gbase = bh * NS * NDH;

        int len;
        {
            const long long* ml = (const long long*)masked_raw;
            long long probe = ml[0];
            if (probe >= 1 && probe <= NS) len = (int)ml[b];
            else                           len = ((const int*)masked_raw)[b];
        }
        const int ntiles = (len + 63) >> 6;

        // Load Q hi into smem
#pragma unroll
        for (int i = 0; i < 4; ++i) {
            int c = tid + i * 256;
            int r = c >> 3, blk = c & 7;
            *(uint4*)(smem + r * QROWB + blk * 16) =
                *(const uint4*)(qh + gbase + (q0 + r) * NDH + blk * 8);
        }

        auto load_kv = [&](int t) {
            const uint32_t s0 = sb + QARR + (t % 3) * KVSTG;
            const int gk = gbase + (t << 6) * NDH;
#pragma unroll
            for (int i = 0; i < 2; ++i) {
                int c = tid + i * 256;
                int r = c >> 3, blk = c & 7;
                const uint32_t dst = s0 + r * QROWB + blk * 16;
                const int src = gk + r * NDH + blk * 8;
                cp_async16(dst,         kh + src);
                cp_async16(dst + KARRA, vh + src);
            }
            cp_commit();
        };

        load_kv(0);
        if (ntiles > 1) load_kv(1);
        __syncthreads();   // Q smem ready

        uint32_t qf[4][4];
        {
            const uint32_t qa = sb + (wid * 16 + (lane & 15)) * QROWB + (lane >> 4) * 16;
#pragma unroll
            for (int ks = 0; ks < 4; ++ks)
                ldsm_x4(qa + ks * 32, qf[ks][0], qf[ks][1], qf[ks][2], qf[ks][3]);
        }

        float m0r = -1e30f, m1r = -1e30f, lsum0 = 0.0f, lsum1 = 0.0f;
        float o[8][4];
#pragma unroll
        for (int di = 0; di < 8; ++di)
#pragma unroll
            for (int q = 0; q < 4; ++q) o[di][q] = 0.0f;

        for (int t = 0; t < ntiles; ++t) {
            if (t + 2 < ntiles) load_kv(t + 2);
            {
                int pend = ntiles - 1 - t;
                if (pend > 2) pend = 2;
                if (pend == 2)      asm volatile("cp.async.wait_group 2;" ::: "memory");
                else if (pend == 1) asm volatile("cp.async.wait_group 1;" ::: "memory");
                else                asm volatile("cp.async.wait_group 0;" ::: "memory");
            }
            __syncthreads();

            const uint32_t kbase = sb + QARR + (t % 3) * KVSTG;

            // ---- S = Q K^T ----
            float s[8][4];
#pragma unroll
            for (int ni = 0; ni < 8; ++ni)
#pragma unroll
                for (int q = 0; q < 4; ++q) s[ni][q] = 0.0f;

#pragma unroll
            for (int ks = 0; ks < 4; ++ks) {
#pragma unroll
                for (int nb = 0; nb < 4; ++nb) {
                    const uint32_t adr = kbase
                        + (nb * 16 + (lane & 7) + 8 * (lane >> 4)) * QROWB
                        + ((lane >> 3) & 1) * 16 + ks * 32;
                    uint32_t t0, t1, t2, t3;
                    ldsm_x4(adr, t0, t1, t2, t3);
                    uint32_t bh0[2] = {t0, t1}, bh1[2] = {t2, t3};
                    mma16816(s[nb*2],   qf[ks], bh0);
                    mma16816(s[nb*2+1], qf[ks], bh1);
                }
            }

            // ---- mask (last tile only) + online softmax (log2 domain) ----
            if (t == ntiles - 1) {
                const int cb = (t << 6) + 2 * (lane & 3);
#pragma unroll
                for (int ni = 0; ni < 8; ++ni) {
                    const int c0 = cb + 8 * ni;
                    if (c0     >= len) { s[ni][0] = -1e30f; s[ni][2] = -1e30f; }
                    if (c0 + 1 >= len) { s[ni][1] = -1e30f; s[ni][3] = -1e30f; }
                }
            }
            float tmax0 = -1e30f, tmax1 = -1e30f;
#pragma unroll
            for (int ni = 0; ni < 8; ++ni) {
                tmax0 = fmaxf(tmax0, fmaxf(s[ni][0], s[ni][1]));
                tmax1 = fmaxf(tmax1, fmaxf(s[ni][2], s[ni][3]));
            }
            tmax0 = fmaxf(tmax0, __shfl_xor_sync(0xffffffffu, tmax0, 1));
            tmax0 = fmaxf(tmax0, __shfl_xor_sync(0xffffffffu, tmax0, 2));
            tmax1 = fmaxf(tmax1, __shfl_xor_sync(0xffffffffu, tmax1, 1));
            tmax1 = fmaxf(tmax1, __shfl_xor_sync(0xffffffffu, tmax1, 2));

            const float mn0 = fmaxf(m0r, tmax0);
            const float mn1 = fmaxf(m1r, tmax1);
            const float sc0 = ex2(m0r - mn0);
            const float sc1 = ex2(m1r - mn1);
            m0r = mn0; m1r = mn1;

            float ps0 = 0.0f, ps1 = 0.0f;
#pragma unroll
            for (int ni = 0; ni < 8; ++ni) {
                float p0 = ex2(s[ni][0] - mn0);
                float p1 = ex2(s[ni][1] - mn0);
                float p2 = ex2(s[ni][2] - mn1);
                float p3 = ex2(s[ni][3] - mn1);
                ps0 += p0 + p1;
                ps1 += p2 + p3;
                s[ni][0] = __uint_as_float(pack_h2(p0, p1));
                s[ni][2] = __uint_as_float(pack_h2(p2, p3));
            }
            ps0 += __shfl_xor_sync(0xffffffffu, ps0, 1);
            ps0 += __shfl_xor_sync(0xffffffffu, ps0, 2);
            ps1 += __shfl_xor_sync(0xffffffffu, ps1, 1);
            ps1 += __shfl_xor_sync(0xffffffffu, ps1, 2);
            lsum0 = lsum0 * sc0 + ps0;
            lsum1 = lsum1 * sc1 + ps1;
#pragma unroll
            for (int di = 0; di < 8; ++di) {
                o[di][0] *= sc0; o[di][1] *= sc0;
                o[di][2] *= sc1; o[di][3] *= sc1;
            }

            // ---- O += P V ----
            const uint32_t vbase = kbase + KARRA;
#pragma unroll
            for (int ks2 = 0; ks2 < 4; ++ks2) {
                uint32_t Ahf[4] = {
                    __float_as_uint(s[2*ks2][0]),   __float_as_uint(s[2*ks2][2]),
                    __float_as_uint(s[2*ks2+1][0]), __float_as_uint(s[2*ks2+1][2]) };
#pragma unroll
                for (int db = 0; db < 4; ++db) {
                    const uint32_t adr = vbase
                        + (ks2 * 16 + (lane & 7) + 8 * ((lane >> 3) & 1)) * QROWB
                        + ((lane >> 4) & 1) * 16 + db * 32;
                    uint32_t t0, t1, t2, t3;
                    ldsm_x4_t(adr, t0, t1, t2, t3);
                    uint32_t vh0[2] = {t0, t1}, vh1[2] = {t2, t3};
                    mma16816(o[db*2],   Ahf, vh0);
                    mma16816(o[db*2+1], Ahf, vh1);
                }
            }
            __syncthreads();
        }

        // ---- normalize + write ctx hi [B,S,D] ----
        const float inv0 = 1.0f / lsum0;
        const float inv1 = 1.0f / lsum1;
        const int r  = lane >> 2;
        const int dc = 2 * (lane & 3);
        const int qrow0 = q0 + wid * 16 + r;
#pragma unroll
        for (int di = 0; di < 8; ++di) {
            const int d = 8 * di + dc;
            *(uint32_t*)&ch[((b * NS + qrow0) * ND) + h * NDH + d] =
                pack_h2(o[di][0] * inv0, o[di][1] * inv0);
            *(uint32_t*)&ch[((b * NS + qrow0 + 8) * ND) + h * NDH + d] =
                pack_h2(o[di][2] * inv1, o[di][3] * inv1);
        }
    }
}

// ---------------------------------------------------------------------------
extern "C" void kernel_launch(void* const* d_in, const int* in_sizes, int n_in,
                              void* d_out, int out_size)
{
    (void)in_sizes; (void)n_in; (void)out_size;
    const float* Q  = (const float*)d_in[0];
    const float* K  = (const float*)d_in[1];
    const float* V  = (const float*)d_in[2];
    const float* Wq = (const float*)d_in[3];
    const float* bq = (const float*)d_in[4];
    const float* Wk = (const float*)d_in[5];
    const float* bk = (const float*)d_in[6];
    const float* Wv = (const float*)d_in[7];
    const float* bv = (const float*)d_in[8];
    const float* Wo = (const float*)d_in[9];
    const float* bo = (const float*)d_in[10];
    const void*  mk = d_in[11];
    float* out = (float*)d_out;

    __half *pqh, *pkh, *pvh, *pch, *pah, *pwh;
    cudaGetSymbolAddress((void**)&pqh, g_qh);
    cudaGetSymbolAddress((void**)&pkh, g_kh);
    cudaGetSymbolAddress((void**)&pvh, g_vh);
    cudaGetSymbolAddress((void**)&pch, g_ch);
    cudaGetSymbolAddress((void**)&pah, g_ah);
    cudaGetSymbolAddress((void**)&pwh, g_wh);

    const int NACT = NB * NS * ND;   // 4194304
    const int NW   = ND * ND;        // 262144
    const int nx4 = NACT / 4;
    const int nw4 = NW / 4;

    cudaFuncSetAttribute((const void*)proj_qkv,
                         cudaFuncAttributeMaxDynamicSharedMemorySize, PROJ_SMEM);
    cudaFuncSetAttribute((const void*)proj_o,
                         cudaFuncAttributeMaxDynamicSharedMemorySize, PROJ_SMEM);
    cudaFuncSetAttribute((const void*)attn_hmma,
                         cudaFuncAttributeMaxDynamicSharedMemorySize, ATTN_SMEM);

    const float QSCALE = 0.125f * 1.4426950408889634f;  // 1/sqrt(64) * log2(e)

    // 1) weight hi conversions (4 in one launch)
    conv_w4<<<dim3((nw4 / 2 + 255) / 256, 4), 256>>>(
        Wq, Wk, Wv, Wo, pwh, pwh + NW, pwh + 2 * NW, pwh + 3 * NW, nw4);
    // 2) activation hi conversions (3 in one launch; also resets g_ctr)
    conv_a3<<<dim3((nx4 / 2 + 255) / 256, 3), 256>>>(
        Q, K, V, pah, pah + NACT, pah + 2 * NACT, nx4);
    // 3) fused Q/K/V projections (persistent z-loop, single wave)
    proj_qkv<<<dim3(64, 4), 256, PROJ_SMEM>>>(
        pah,            pwh,          bq, pqh, QSCALE,
        pah + NACT,     pwh + NW,     bk, pkh,
        pah + 2 * NACT, pwh + 2 * NW, bv, pvh);
    // 4) attention (persistent work-stealing, one wave of 296 CTAs)
    attn_hmma<<<296, 256, ATTN_SMEM>>>(pqh, pkh, pvh, pch, mk);
    // 5) output projection
    proj_o<<<dim3(64, 4), 256, PROJ_SMEM>>>(
        pch, pwh + 3 * NW, bo, out);
}

// round 16
// speedup vs baseline: 1.0597x; 1.0597x over previous
#include <cuda_runtime.h>
#include <cuda_fp16.h>
#include <cstdint>

#define NB  4
#define NS  2048
#define ND  512
#define NH  8
#define NDH 64

// ---------------------------------------------------------------------------
// Scratch (device globals: allocation-free rule)
// ---------------------------------------------------------------------------
__device__ __half g_qh[NB * NH * NS * NDH];   // hi only (pre-scaled)
__device__ __half g_kh[NB * NH * NS * NDH];   // hi only
__device__ __half g_vh[NB * NH * NS * NDH];   // hi only
__device__ __half g_ch[NB * NS * ND];         // ctx hi only
__device__ __half g_ah[3][NB * NS * ND];      // Q/K/V activation hi
__device__ __half g_wh[4][ND * ND];           // Wq,Wk,Wv,Wo hi

// ---------------------------------------------------------------------------
__device__ __forceinline__ uint32_t smem_u32(const void* p) {
    uint32_t a;
    asm("{ .reg .u64 t; cvta.to.shared.u64 t, %1; cvt.u32.u64 %0, t; }"
        : "=r"(a) : "l"(p));
    return a;
}
__device__ __forceinline__ void cp_async16(uint32_t dst, const void* src) {
    asm volatile("cp.async.ca.shared.global [%0], [%1], 16;"
                 :: "r"(dst), "l"(src) : "memory");
}
__device__ __forceinline__ void cp_commit() {
    asm volatile("cp.async.commit_group;" ::: "memory");
}
__device__ __forceinline__ void ldsm_x4(uint32_t addr, uint32_t& r0, uint32_t& r1,
                                        uint32_t& r2, uint32_t& r3) {
    asm volatile("ldmatrix.sync.aligned.m8n8.x4.shared.b16 {%0,%1,%2,%3}, [%4];"
                 : "=r"(r0), "=r"(r1), "=r"(r2), "=r"(r3) : "r"(addr));
}
__device__ __forceinline__ void ldsm_x4_t(uint32_t addr, uint32_t& r0, uint32_t& r1,
                                          uint32_t& r2, uint32_t& r3) {
    asm volatile("ldmatrix.sync.aligned.m8n8.x4.trans.shared.b16 {%0,%1,%2,%3}, [%4];"
                 : "=r"(r0), "=r"(r1), "=r"(r2), "=r"(r3) : "r"(addr));
}
__device__ __forceinline__ void mma16816(float* c, const uint32_t* a, const uint32_t* b) {
    asm volatile(
        "mma.sync.aligned.m16n8k16.row.col.f32.f16.f16.f32 "
        "{%0,%1,%2,%3}, {%4,%5,%6,%7}, {%8,%9}, {%0,%1,%2,%3};"
        : "+f"(c[0]), "+f"(c[1]), "+f"(c[2]), "+f"(c[3])
        : "r"(a[0]), "r"(a[1]), "r"(a[2]), "r"(a[3]), "r"(b[0]), "r"(b[1]));
}
__device__ __forceinline__ float ex2(float x) {
    float y;
    asm("ex2.approx.ftz.f32 %0, %1;" : "=f"(y) : "f"(x));
    return y;
}
__device__ __forceinline__ uint32_t pack_h2(float a, float b) {
    __half2 t = __floats2half2_rn(a, b);
    return *(uint32_t*)&t;
}

// ---------------------------------------------------------------------------
// Merged conversions (fp32 -> fp16 hi), 2 x float4 per thread
// ---------------------------------------------------------------------------
__device__ __forceinline__ void conv8(const float* in, __half* hi, int idx, int n4) {
#pragma unroll
    for (int j = 0; j < 2; ++j) {
        int i = idx + j;
        if (i < n4) {
            float4 v = ((const float4*)in)[i];
            __half h[4] = {__float2half_rn(v.x), __float2half_rn(v.y),
                           __float2half_rn(v.z), __float2half_rn(v.w)};
            ((uint2*)hi)[i] = *(uint2*)h;
        }
    }
}

__global__ __launch_bounds__(256) void conv_w4(
    const float* w0, const float* w1, const float* w2, const float* w3,
    __half* h0, __half* h1, __half* h2, __half* h3, int n4)
{
    const float* in; __half* hi;
    switch (blockIdx.y) {
        case 0:  in = w0; hi = h0; break;
        case 1:  in = w1; hi = h1; break;
        case 2:  in = w2; hi = h2; break;
        default: in = w3; hi = h3; break;
    }
    conv8(in, hi, (blockIdx.x * 256 + threadIdx.x) * 2, n4);
}

__global__ __launch_bounds__(256) void conv_a3(
    const float* a0, const float* a1, const float* a2,
    __half* h0, __half* h1, __half* h2, int n4)
{
    const float* in; __half* hi;
    switch (blockIdx.y) {
        case 0:  in = a0; hi = h0; break;
        case 1:  in = a1; hi = h1; break;
        default: in = a2; hi = h2; break;
    }
    conv8(in, hi, (blockIdx.x * 256 + threadIdx.x) * 2, n4);
}

// ---------------------------------------------------------------------------
// HMMA projection GEMM body: C[8192,512] = X @ W^T + bias
// 256 threads, 8 warps (4m x 2n), warp tile 32x64, BK=64.
// Depth-3 cp.async ring, ONE barrier per chunk. Prefetch for chunk c+2 is
// issued AFTER iter c's barrier, so its target stage ((c-1)%3) has been
// fully consumed (readers of iter c-1 all passed this barrier). 2 CTAs/SM.
// MODE 0: fp32 row-major out. MODE 1: fp16 hi out, head layout, scaled.
// ---------------------------------------------------------------------------
#define ROWB   144           // 64 halves (128B) + 16B pad
#define ARRSZ  (128 * ROWB)  // 18432
#define STG    (2 * ARRSZ)   // 36864 per stage (A + B)
#define PROJ_SMEM (3 * STG)  // 110592

template <int MODE>
__device__ __forceinline__ void proj_body(
    const __half* __restrict__ Ah, const __half* __restrict__ Bh,
    const float* __restrict__ bias, float* __restrict__ outF,
    __half* __restrict__ outH, float scale, char* smem)
{
    const uint32_t sb = smem_u32(smem);
    const int tid  = threadIdx.x;
    const int lane = tid & 31;
    const int wid  = tid >> 5;
    const int warp_m = wid & 3;
    const int warp_n = wid >> 2;
    const int m0 = blockIdx.x * 128;
    const int n0 = blockIdx.y * 128;

    const uint32_t a_off = (uint32_t)((warp_m * 32 + (lane & 15)) * ROWB + (lane >> 4) * 16);
    const uint32_t b_off = (uint32_t)((warp_n * 64 + (lane & 7) + 8 * (lane >> 4)) * ROWB
                                      + ((lane >> 3) & 1) * 16);

    float acc[2][8][4];
#pragma unroll
    for (int mi = 0; mi < 2; ++mi)
#pragma unroll
        for (int ni = 0; ni < 8; ++ni)
#pragma unroll
            for (int q = 0; q < 4; ++q) acc[mi][ni][q] = 0.0f;

    auto load_chunk = [&](int c) {
        const int k0 = c * 64;
        const uint32_t st = sb + (c % 3) * STG;
#pragma unroll
        for (int i = 0; i < 4; ++i) {
            const int c2 = tid + i * 256;
            const int r  = c2 >> 3;
            const int g  = c2 & 7;
            cp_async16(st + r * ROWB + g * 16,
                       Ah + (m0 + r) * ND + k0 + g * 8);
            cp_async16(st + ARRSZ + r * ROWB + g * 16,
                       Bh + (n0 + r) * ND + k0 + g * 8);
        }
        cp_commit();
    };

    load_chunk(0);
    load_chunk(1);

    for (int c = 0; c < 8; ++c) {
        // outstanding groups entering iter c: {c, c+1} -> allow 1 pending
        if (c < 7) asm volatile("cp.async.wait_group 1;" ::: "memory");
        else       asm volatile("cp.async.wait_group 0;" ::: "memory");
        __syncthreads();   // all readers of stage (c-1)%3 have finished
        if (c + 2 < 8) load_chunk(c + 2);   // safe: writes stage (c-1)%3

        const uint32_t st = sb + (c % 3) * STG;
#pragma unroll
        for (int ks = 0; ks < 4; ++ks) {
            const uint32_t kb = ks * 32;
            uint32_t ah[2][4];
#pragma unroll
            for (int mi = 0; mi < 2; ++mi) {
                uint32_t adr = st + a_off + mi * (16 * ROWB) + kb;
                ldsm_x4(adr, ah[mi][0], ah[mi][1], ah[mi][2], ah[mi][3]);
            }
#pragma unroll
            for (int nb = 0; nb < 4; ++nb) {
                uint32_t adr = st + ARRSZ + b_off + nb * (16 * ROWB) + kb;
                uint32_t t0, t1, t2, t3;
                ldsm_x4(adr, t0, t1, t2, t3);
                uint32_t bhA[2] = {t0, t1}, bhB[2] = {t2, t3};
#pragma unroll
                for (int mi = 0; mi < 2; ++mi) {
                    mma16816(acc[mi][nb*2],   ah[mi], bhA);
                    mma16816(acc[mi][nb*2+1], ah[mi], bhB);
                }
            }
        }
    }

    const int crow = lane >> 2;
    const int ccol = (lane & 3) * 2;
#pragma unroll
    for (int mi = 0; mi < 2; ++mi) {
#pragma unroll
        for (int half = 0; half < 2; ++half) {
            const int m = m0 + warp_m * 32 + mi * 16 + crow + half * 8;
            const int b = m >> 11, s = m & 2047;
#pragma unroll
            for (int ni = 0; ni < 8; ++ni) {
                const int n = n0 + warp_n * 64 + ni * 8 + ccol;
                float v0 = acc[mi][ni][half * 2 + 0] + bias[n];
                float v1 = acc[mi][ni][half * 2 + 1] + bias[n + 1];
                if (MODE == 1) {
                    v0 *= scale; v1 *= scale;
                    const int head = n >> 6, d = n & 63;
                    const int idx = ((b * NH + head) * NS + s) * NDH + d;
                    *(uint32_t*)&outH[idx] = pack_h2(v0, v1);
                } else {
                    *(float2*)&outF[m * ND + n] = make_float2(v0, v1);
                }
            }
        }
    }
}

// Fused Q/K/V projections, persistent z-loop: grid (64,4), one wave.
__global__ __launch_bounds__(256, 2) void proj_qkv(
    const __half* AhQ, const __half* BhQ, const float* biasQ, __half* outQ, float scaleQ,
    const __half* AhK, const __half* BhK, const float* biasK, __half* outK,
    const __half* AhV, const __half* BhV, const float* biasV, __half* outV)
{
    extern __shared__ char smem[];
#pragma unroll 1
    for (int z = 0; z < 3; ++z) {
        const __half *Ah, *Bh; const float* bias; __half* outH; float scale;
        if (z == 0)      { Ah = AhQ; Bh = BhQ; bias = biasQ; outH = outQ; scale = scaleQ; }
        else if (z == 1) { Ah = AhK; Bh = BhK; bias = biasK; outH = outK; scale = 1.0f; }
        else             { Ah = AhV; Bh = BhV; bias = biasV; outH = outV; scale = 1.0f; }
        proj_body<1>(Ah, Bh, bias, nullptr, outH, scale, smem);
        __syncthreads();   // epilogue done before next z reuses stages
    }
}

// Output projection, fp32 out
__global__ __launch_bounds__(256, 2) void proj_o(
    const __half* Ah, const __half* Bh, const float* bias, float* outF)
{
    extern __shared__ char smem[];
    proj_body<0>(Ah, Bh, bias, outF, nullptr, 1.0f, smem);
}

// ---------------------------------------------------------------------------
// HMMA flash attention. CTA = 128 q rows x one (b,h), 8 warps, KV tile 64,
// depth-3 cp.async ring, ONE barrier per tile (prefetch issued after the
// barrier -> race-free), 2 CTAs/SM. q/k/v/P/ctx fp16 hi; log2 softmax;
// mask on last KV tile only.
// ---------------------------------------------------------------------------
#define QROWB 144
#define QARR  18432
#define KARRA 9216
#define KVSTG (2 * KARRA)                 // 18432 per stage
#define ATTN_SMEM (QARR + 3 * KVSTG)      // 73728

__global__ __launch_bounds__(256, 2) void attn_hmma(
    const __half* __restrict__ qh,
    const __half* __restrict__ kh, const __half* __restrict__ vh,
    __half* __restrict__ ch,
    const void* __restrict__ masked_raw)
{
    extern __shared__ char smem[];
    const uint32_t sb = smem_u32(smem);
    const int tid  = threadIdx.x;
    const int lane = tid & 31;
    const int wid  = tid >> 5;
    const int bh   = blockIdx.y;
    const int b    = bh >> 3;
    const int h    = bh & 7;
    const int q0   = blockIdx.x << 7;
    const int gbase = bh * NS * NDH;

    int len;
    {
        const long long* ml = (const long long*)masked_raw;
        long long probe = ml[0];
        if (probe >= 1 && probe <= NS) len = (int)ml[b];
        else                           len = ((const int*)masked_raw)[b];
    }
    const int ntiles = (len + 63) >> 6;

    // Load Q hi into smem
#pragma unroll
    for (int i = 0; i < 4; ++i) {
        int c = tid + i * 256;
        int r = c >> 3, blk = c & 7;
        *(uint4*)(smem + r * QROWB + blk * 16) =
            *(const uint4*)(qh + gbase + (q0 + r) * NDH + blk * 8);
    }

    auto load_kv = [&](int t) {
        const uint32_t s0 = sb + QARR + (t % 3) * KVSTG;
        const int gk = gbase + (t << 6) * NDH;
#pragma unroll
        for (int i = 0; i < 2; ++i) {
            int c = tid + i * 256;
            int r = c >> 3, blk = c & 7;
            const uint32_t dst = s0 + r * QROWB + blk * 16;
            const int src = gk + r * NDH + blk * 8;
            cp_async16(dst,         kh + src);
            cp_async16(dst + KARRA, vh + src);
        }
        cp_commit();
    };

    load_kv(0);
    if (ntiles > 1) load_kv(1);
    __syncthreads();   // Q smem ready

    uint32_t qf[4][4];
    {
        const uint32_t qa = sb + (wid * 16 + (lane & 15)) * QROWB + (lane >> 4) * 16;
#pragma unroll
        for (int ks = 0; ks < 4; ++ks)
            ldsm_x4(qa + ks * 32, qf[ks][0], qf[ks][1], qf[ks][2], qf[ks][3]);
    }

    float m0r = -1e30f, m1r = -1e30f, lsum0 = 0.0f, lsum1 = 0.0f;
    float o[8][4];
#pragma unroll
    for (int di = 0; di < 8; ++di)
#pragma unroll
        for (int q = 0; q < 4; ++q) o[di][q] = 0.0f;

    for (int t = 0; t < ntiles; ++t) {
        // outstanding groups entering iter t: {t, t+1 (if issued)}
        if (t + 1 < ntiles) asm volatile("cp.async.wait_group 1;" ::: "memory");
        else                asm volatile("cp.async.wait_group 0;" ::: "memory");
        __syncthreads();   // readers of stage (t-1)%3 have all finished
        if (t + 2 < ntiles) load_kv(t + 2);   // safe: writes stage (t-1)%3

        const uint32_t kbase = sb + QARR + (t % 3) * KVSTG;

        // ---- S = Q K^T ----
        float s[8][4];
#pragma unroll
        for (int ni = 0; ni < 8; ++ni)
#pragma unroll
            for (int q = 0; q < 4; ++q) s[ni][q] = 0.0f;

#pragma unroll
        for (int ks = 0; ks < 4; ++ks) {
#pragma unroll
            for (int nb = 0; nb < 4; ++nb) {
                const uint32_t adr = kbase
                    + (nb * 16 + (lane & 7) + 8 * (lane >> 4)) * QROWB
                    + ((lane >> 3) & 1) * 16 + ks * 32;
                uint32_t t0, t1, t2, t3;
                ldsm_x4(adr, t0, t1, t2, t3);
                uint32_t bh0[2] = {t0, t1}, bh1[2] = {t2, t3};
                mma16816(s[nb*2],   qf[ks], bh0);
                mma16816(s[nb*2+1], qf[ks], bh1);
            }
        }

        // ---- mask (last tile only) + online softmax (log2 domain) ----
        if (t == ntiles - 1) {
            const int cb = (t << 6) + 2 * (lane & 3);
#pragma unroll
            for (int ni = 0; ni < 8; ++ni) {
                const int c0 = cb + 8 * ni;
                if (c0     >= len) { s[ni][0] = -1e30f; s[ni][2] = -1e30f; }
                if (c0 + 1 >= len) { s[ni][1] = -1e30f; s[ni][3] = -1e30f; }
            }
        }
        float tmax0 = -1e30f, tmax1 = -1e30f;
#pragma unroll
        for (int ni = 0; ni < 8; ++ni) {
            tmax0 = fmaxf(tmax0, fmaxf(s[ni][0], s[ni][1]));
            tmax1 = fmaxf(tmax1, fmaxf(s[ni][2], s[ni][3]));
        }
        tmax0 = fmaxf(tmax0, __shfl_xor_sync(0xffffffffu, tmax0, 1));
        tmax0 = fmaxf(tmax0, __shfl_xor_sync(0xffffffffu, tmax0, 2));
        tmax1 = fmaxf(tmax1, __shfl_xor_sync(0xffffffffu, tmax1, 1));
        tmax1 = fmaxf(tmax1, __shfl_xor_sync(0xffffffffu, tmax1, 2));

        const float mn0 = fmaxf(m0r, tmax0);
        const float mn1 = fmaxf(m1r, tmax1);
        const float sc0 = ex2(m0r - mn0);
        const float sc1 = ex2(m1r - mn1);
        m0r = mn0; m1r = mn1;

        float ps0 = 0.0f, ps1 = 0.0f;
#pragma unroll
        for (int ni = 0; ni < 8; ++ni) {
            float p0 = ex2(s[ni][0] - mn0);
            float p1 = ex2(s[ni][1] - mn0);
            float p2 = ex2(s[ni][2] - mn1);
            float p3 = ex2(s[ni][3] - mn1);
            ps0 += p0 + p1;
            ps1 += p2 + p3;
            s[ni][0] = __uint_as_float(pack_h2(p0, p1));
            s[ni][2] = __uint_as_float(pack_h2(p2, p3));
        }
        ps0 += __shfl_xor_sync(0xffffffffu, ps0, 1);
        ps0 += __shfl_xor_sync(0xffffffffu, ps0, 2);
        ps1 += __shfl_xor_sync(0xffffffffu, ps1, 1);
        ps1 += __shfl_xor_sync(0xffffffffu, ps1, 2);
        lsum0 = lsum0 * sc0 + ps0;
        lsum1 = lsum1 * sc1 + ps1;
#pragma unroll
        for (int di = 0; di < 8; ++di) {
            o[di][0] *= sc0; o[di][1] *= sc0;
            o[di][2] *= sc1; o[di][3] *= sc1;
        }

        // ---- O += P V ----
        const uint32_t vbase = kbase + KARRA;
#pragma unroll
        for (int ks2 = 0; ks2 < 4; ++ks2) {
            uint32_t Ahf[4] = {
                __float_as_uint(s[2*ks2][0]),   __float_as_uint(s[2*ks2][2]),
                __float_as_uint(s[2*ks2+1][0]), __float_as_uint(s[2*ks2+1][2]) };
#pragma unroll
            for (int db = 0; db < 4; ++db) {
                const uint32_t adr = vbase
                    + (ks2 * 16 + (lane & 7) + 8 * ((lane >> 3) & 1)) * QROWB
                    + ((lane >> 4) & 1) * 16 + db * 32;
                uint32_t t0, t1, t2, t3;
                ldsm_x4_t(adr, t0, t1, t2, t3);
                uint32_t vh0[2] = {t0, t1}, vh1[2] = {t2, t3};
                mma16816(o[db*2],   Ahf, vh0);
                mma16816(o[db*2+1], Ahf, vh1);
            }
        }
        // no trailing barrier: next iteration's leading barrier orders these
        // reads before any prefetch issued after it overwrites this stage.
    }

    // ---- normalize + write ctx hi [B,S,D] ----
    const float inv0 = 1.0f / lsum0;
    const float inv1 = 1.0f / lsum1;
    const int r  = lane >> 2;
    const int dc = 2 * (lane & 3);
    const int qrow0 = q0 + wid * 16 + r;
#pragma unroll
    for (int di = 0; di < 8; ++di) {
        const int d = 8 * di + dc;
        *(uint32_t*)&ch[((b * NS + qrow0) * ND) + h * NDH + d] =
            pack_h2(o[di][0] * inv0, o[di][1] * inv0);
        *(uint32_t*)&ch[((b * NS + qrow0 + 8) * ND) + h * NDH + d] =
            pack_h2(o[di][2] * inv1, o[di][3] * inv1);
    }
}

// ---------------------------------------------------------------------------
extern "C" void kernel_launch(void* const* d_in, const int* in_sizes, int n_in,
                              void* d_out, int out_size)
{
    (void)in_sizes; (void)n_in; (void)out_size;
    const float* Q  = (const float*)d_in[0];
    const float* K  = (const float*)d_in[1];
    const float* V  = (const float*)d_in[2];
    const float* Wq = (const float*)d_in[3];
    const float* bq = (const float*)d_in[4];
    const float* Wk = (const float*)d_in[5];
    const float* bk = (const float*)d_in[6];
    const float* Wv = (const float*)d_in[7];
    const float* bv = (const float*)d_in[8];
    const float* Wo = (const float*)d_in[9];
    const float* bo = (const float*)d_in[10];
    const void*  mk = d_in[11];
    float* out = (float*)d_out;

    __half *pqh, *pkh, *pvh, *pch, *pah, *pwh;
    cudaGetSymbolAddress((void**)&pqh, g_qh);
    cudaGetSymbolAddress((void**)&pkh, g_kh);
    cudaGetSymbolAddress((void**)&pvh, g_vh);
    cudaGetSymbolAddress((void**)&pch, g_ch);
    cudaGetSymbolAddress((void**)&pah, g_ah);
    cudaGetSymbolAddress((void**)&pwh, g_wh);

    const int NACT = NB * NS * ND;   // 4194304
    const int NW   = ND * ND;        // 262144
    const int nx4 = NACT / 4;
    const int nw4 = NW / 4;

    cudaFuncSetAttribute((const void*)proj_qkv,
                         cudaFuncAttributeMaxDynamicSharedMemorySize, PROJ_SMEM);
    cudaFuncSetAttribute((const void*)proj_o,
                         cudaFuncAttributeMaxDynamicSharedMemorySize, PROJ_SMEM);
    cudaFuncSetAttribute((const void*)attn_hmma,
                         cudaFuncAttributeMaxDynamicSharedMemorySize, ATTN_SMEM);

    const float QSCALE = 0.125f * 1.4426950408889634f;  // 1/sqrt(64) * log2(e)

    // 1) weight hi conversions (4 in one launch)
    conv_w4<<<dim3((nw4 / 2 + 255) / 256, 4), 256>>>(
        Wq, Wk, Wv, Wo, pwh, pwh + NW, pwh + 2 * NW, pwh + 3 * NW, nw4);
    // 2) activation hi conversions (3 in one launch)
    conv_a3<<<dim3((nx4 / 2 + 255) / 256, 3), 256>>>(
        Q, K, V, pah, pah + NACT, pah + 2 * NACT, nx4);
    // 3) fused Q/K/V projections (persistent z-loop, single wave)
    proj_qkv<<<dim3(64, 4), 256, PROJ_SMEM>>>(
        pah,            pwh,          bq, pqh, QSCALE,
        pah + NACT,     pwh + NW,     bk, pkh,
        pah + 2 * NACT, pwh + 2 * NW, bv, pvh);
    // 4) attention
    attn_hmma<<<dim3(NS / 128, NB * NH), 256, ATTN_SMEM>>>(
        pqh, pkh, pvh, pch, mk);
    // 5) output projection
    proj_o<<<dim3(64, 4), 256, PROJ_SMEM>>>(
        pch, pwh + 3 * NW, bo, out);
}

// round 17
// speedup vs baseline: 1.1655x; 1.0999x over previous
#include <cuda_runtime.h>
#include <cuda_fp16.h>
#include <cstdint>

#define NB  4
#define NS  2048
#define ND  512
#define NH  8
#define NDH 64

// ---------------------------------------------------------------------------
// Scratch (device globals: allocation-free rule)
// ---------------------------------------------------------------------------
__device__ __half g_qh[NB * NH * NS * NDH];   // hi only (pre-scaled)
__device__ __half g_kh[NB * NH * NS * NDH];   // hi only
__device__ __half g_vh[NB * NH * NS * NDH];   // hi only
__device__ __half g_ch[NB * NS * ND];         // ctx hi only
__device__ __half g_ah[3][NB * NS * ND];      // Q/K/V activation hi
__device__ __half g_wh[4][ND * ND];           // Wq,Wk,Wv,Wo hi

// ---------------------------------------------------------------------------
__device__ __forceinline__ uint32_t smem_u32(const void* p) {
    uint32_t a;
    asm("{ .reg .u64 t; cvta.to.shared.u64 t, %1; cvt.u32.u64 %0, t; }"
        : "=r"(a) : "l"(p));
    return a;
}
__device__ __forceinline__ void cp_async16(uint32_t dst, const void* src) {
    asm volatile("cp.async.ca.shared.global [%0], [%1], 16;"
                 :: "r"(dst), "l"(src) : "memory");
}
__device__ __forceinline__ void cp_commit() {
    asm volatile("cp.async.commit_group;" ::: "memory");
}
__device__ __forceinline__ void ldsm_x4(uint32_t addr, uint32_t& r0, uint32_t& r1,
                                        uint32_t& r2, uint32_t& r3) {
    asm volatile("ldmatrix.sync.aligned.m8n8.x4.shared.b16 {%0,%1,%2,%3}, [%4];"
                 : "=r"(r0), "=r"(r1), "=r"(r2), "=r"(r3) : "r"(addr));
}
__device__ __forceinline__ void ldsm_x4_t(uint32_t addr, uint32_t& r0, uint32_t& r1,
                                          uint32_t& r2, uint32_t& r3) {
    asm volatile("ldmatrix.sync.aligned.m8n8.x4.trans.shared.b16 {%0,%1,%2,%3}, [%4];"
                 : "=r"(r0), "=r"(r1), "=r"(r2), "=r"(r3) : "r"(addr));
}
__device__ __forceinline__ void mma16816(float* c, const uint32_t* a, const uint32_t* b) {
    asm volatile(
        "mma.sync.aligned.m16n8k16.row.col.f32.f16.f16.f32 "
        "{%0,%1,%2,%3}, {%4,%5,%6,%7}, {%8,%9}, {%0,%1,%2,%3};"
        : "+f"(c[0]), "+f"(c[1]), "+f"(c[2]), "+f"(c[3])
        : "r"(a[0]), "r"(a[1]), "r"(a[2]), "r"(a[3]), "r"(b[0]), "r"(b[1]));
}
__device__ __forceinline__ float ex2(float x) {
    float y;
    asm("ex2.approx.ftz.f32 %0, %1;" : "=f"(y) : "f"(x));
    return y;
}
__device__ __forceinline__ uint32_t pack_h2(float a, float b) {
    __half2 t = __floats2half2_rn(a, b);
    return *(uint32_t*)&t;
}

// ---------------------------------------------------------------------------
// Merged conversions (fp32 -> fp16 hi), 2 x float4 per thread
// ---------------------------------------------------------------------------
__device__ __forceinline__ void conv8(const float* in, __half* hi, int idx, int n4) {
#pragma unroll
    for (int j = 0; j < 2; ++j) {
        int i = idx + j;
        if (i < n4) {
            float4 v = ((const float4*)in)[i];
            __half h[4] = {__float2half_rn(v.x), __float2half_rn(v.y),
                           __float2half_rn(v.z), __float2half_rn(v.w)};
            ((uint2*)hi)[i] = *(uint2*)h;
        }
    }
}

__global__ __launch_bounds__(256) void conv_w4(
    const float* w0, const float* w1, const float* w2, const float* w3,
    __half* h0, __half* h1, __half* h2, __half* h3, int n4)
{
    const float* in; __half* hi;
    switch (blockIdx.y) {
        case 0:  in = w0; hi = h0; break;
        case 1:  in = w1; hi = h1; break;
        case 2:  in = w2; hi = h2; break;
        default: in = w3; hi = h3; break;
    }
    conv8(in, hi, (blockIdx.x * 256 + threadIdx.x) * 2, n4);
}

__global__ __launch_bounds__(256) void conv_a3(
    const float* a0, const float* a1, const float* a2,
    __half* h0, __half* h1, __half* h2, int n4)
{
    const float* in; __half* hi;
    switch (blockIdx.y) {
        case 0:  in = a0; hi = h0; break;
        case 1:  in = a1; hi = h1; break;
        default: in = a2; hi = h2; break;
    }
    conv8(in, hi, (blockIdx.x * 256 + threadIdx.x) * 2, n4);
}

// ---------------------------------------------------------------------------
// HMMA projection GEMM body (R12-proven): C[8192,512] = X @ W^T + bias
// 256 threads, 8 warps (4m x 2n), warp tile 32x64, BK=64, depth-2 double
// buffer, prefetch issued BEFORE wait into the opposite stage, two barriers
// per chunk (trailing barrier protects the stage the next prefetch writes).
// 2 CTAs/SM. MODE 0: fp32 out. MODE 1: fp16 hi out, head layout, scaled.
// ---------------------------------------------------------------------------
#define ROWB   144           // 64 halves (128B) + 16B pad
#define ARRSZ  (128 * ROWB)  // 18432
#define STG    (2 * ARRSZ)   // 36864 per stage (A + B)
#define PROJ_SMEM (2 * STG)  // 73728

template <int MODE>
__device__ __forceinline__ void proj_body(
    const __half* __restrict__ Ah, const __half* __restrict__ Bh,
    const float* __restrict__ bias, float* __restrict__ outF,
    __half* __restrict__ outH, float scale, char* smem)
{
    const uint32_t sb = smem_u32(smem);
    const int tid  = threadIdx.x;
    const int lane = tid & 31;
    const int wid  = tid >> 5;
    const int warp_m = wid & 3;
    const int warp_n = wid >> 2;
    const int m0 = blockIdx.x * 128;
    const int n0 = blockIdx.y * 128;

    const uint32_t a_off = (uint32_t)((warp_m * 32 + (lane & 15)) * ROWB + (lane >> 4) * 16);
    const uint32_t b_off = (uint32_t)((warp_n * 64 + (lane & 7) + 8 * (lane >> 4)) * ROWB
                                      + ((lane >> 3) & 1) * 16);

    float acc[2][8][4];
#pragma unroll
    for (int mi = 0; mi < 2; ++mi)
#pragma unroll
        for (int ni = 0; ni < 8; ++ni)
#pragma unroll
            for (int q = 0; q < 4; ++q) acc[mi][ni][q] = 0.0f;

    auto load_chunk = [&](int c, int stage) {
        const int k0 = c * 64;
        const uint32_t st = sb + stage * STG;
#pragma unroll
        for (int i = 0; i < 4; ++i) {
            const int c2 = tid + i * 256;
            const int r  = c2 >> 3;
            const int g  = c2 & 7;
            cp_async16(st + r * ROWB + g * 16,
                       Ah + (m0 + r) * ND + k0 + g * 8);
            cp_async16(st + ARRSZ + r * ROWB + g * 16,
                       Bh + (n0 + r) * ND + k0 + g * 8);
        }
        cp_commit();
    };

    load_chunk(0, 0);

    for (int c = 0; c < 8; ++c) {
        const int stage = c & 1;
        if (c < 7) {
            load_chunk(c + 1, stage ^ 1);
            asm volatile("cp.async.wait_group 1;" ::: "memory");
        } else {
            asm volatile("cp.async.wait_group 0;" ::: "memory");
        }
        __syncthreads();

        const uint32_t st = sb + stage * STG;
#pragma unroll
        for (int ks = 0; ks < 4; ++ks) {
            const uint32_t kb = ks * 32;
            uint32_t ah[2][4];
#pragma unroll
            for (int mi = 0; mi < 2; ++mi) {
                uint32_t adr = st + a_off + mi * (16 * ROWB) + kb;
                ldsm_x4(adr, ah[mi][0], ah[mi][1], ah[mi][2], ah[mi][3]);
            }
#pragma unroll
            for (int nb = 0; nb < 4; ++nb) {
                uint32_t adr = st + ARRSZ + b_off + nb * (16 * ROWB) + kb;
                uint32_t t0, t1, t2, t3;
                ldsm_x4(adr, t0, t1, t2, t3);
                uint32_t bhA[2] = {t0, t1}, bhB[2] = {t2, t3};
#pragma unroll
                for (int mi = 0; mi < 2; ++mi) {
                    mma16816(acc[mi][nb*2],   ah[mi], bhA);
                    mma16816(acc[mi][nb*2+1], ah[mi], bhB);
                }
            }
        }
        __syncthreads();   // readers done before next prefetch overwrites
    }

    const int crow = lane >> 2;
    const int ccol = (lane & 3) * 2;
#pragma unroll
    for (int mi = 0; mi < 2; ++mi) {
#pragma unroll
        for (int half = 0; half < 2; ++half) {
            const int m = m0 + warp_m * 32 + mi * 16 + crow + half * 8;
            const int b = m >> 11, s = m & 2047;
#pragma unroll
            for (int ni = 0; ni < 8; ++ni) {
                const int n = n0 + warp_n * 64 + ni * 8 + ccol;
                float v0 = acc[mi][ni][half * 2 + 0] + bias[n];
                float v1 = acc[mi][ni][half * 2 + 1] + bias[n + 1];
                if (MODE == 1) {
                    v0 *= scale; v1 *= scale;
                    const int head = n >> 6, d = n & 63;
                    const int idx = ((b * NH + head) * NS + s) * NDH + d;
                    *(uint32_t*)&outH[idx] = pack_h2(v0, v1);
                } else {
                    *(float2*)&outF[m * ND + n] = make_float2(v0, v1);
                }
            }
        }
    }
}

// Fused Q/K/V projections, persistent z-loop: grid (64,4), one wave.
__global__ __launch_bounds__(256, 2) void proj_qkv(
    const __half* AhQ, const __half* BhQ, const float* biasQ, __half* outQ, float scaleQ,
    const __half* AhK, const __half* BhK, const float* biasK, __half* outK,
    const __half* AhV, const __half* BhV, const float* biasV, __half* outV)
{
    extern __shared__ char smem[];
#pragma unroll 1
    for (int z = 0; z < 3; ++z) {
        const __half *Ah, *Bh; const float* bias; __half* outH; float scale;
        if (z == 0)      { Ah = AhQ; Bh = BhQ; bias = biasQ; outH = outQ; scale = scaleQ; }
        else if (z == 1) { Ah = AhK; Bh = BhK; bias = biasK; outH = outK; scale = 1.0f; }
        else             { Ah = AhV; Bh = BhV; bias = biasV; outH = outV; scale = 1.0f; }
        proj_body<1>(Ah, Bh, bias, nullptr, outH, scale, smem);
        __syncthreads();
    }
}

// Output projection, fp32 out
__global__ __launch_bounds__(256, 2) void proj_o(
    const __half* Ah, const __half* Bh, const float* bias, float* outF)
{
    extern __shared__ char smem[];
    proj_body<0>(Ah, Bh, bias, outF, nullptr, 1.0f, smem);
}

// ---------------------------------------------------------------------------
// HMMA flash attention (R16-proven). CTA = 128 q rows x one (b,h), 8 warps,
// KV tile 64, depth-3 cp.async ring, ONE barrier per tile (prefetch issued
// after the barrier -> race-free), 2 CTAs/SM. q/k/v/P/ctx fp16 hi;
// log2-domain softmax; mask on last KV tile only.
// ---------------------------------------------------------------------------
#define QROWB 144
#define QARR  18432
#define KARRA 9216
#define KVSTG (2 * KARRA)                 // 18432 per stage
#define ATTN_SMEM (QARR + 3 * KVSTG)      // 73728

__global__ __launch_bounds__(256, 2) void attn_hmma(
    const __half* __restrict__ qh,
    const __half* __restrict__ kh, const __half* __restrict__ vh,
    __half* __restrict__ ch,
    const void* __restrict__ masked_raw)
{
    extern __shared__ char smem[];
    const uint32_t sb = smem_u32(smem);
    const int tid  = threadIdx.x;
    const int lane = tid & 31;
    const int wid  = tid >> 5;
    const int bh   = blockIdx.y;
    const int b    = bh >> 3;
    const int h    = bh & 7;
    const int q0   = blockIdx.x << 7;
    const int gbase = bh * NS * NDH;

    int len;
    {
        const long long* ml = (const long long*)masked_raw;
        long long probe = ml[0];
        if (probe >= 1 && probe <= NS) len = (int)ml[b];
        else                           len = ((const int*)masked_raw)[b];
    }
    const int ntiles = (len + 63) >> 6;

    // Load Q hi into smem
#pragma unroll
    for (int i = 0; i < 4; ++i) {
        int c = tid + i * 256;
        int r = c >> 3, blk = c & 7;
        *(uint4*)(smem + r * QROWB + blk * 16) =
            *(const uint4*)(qh + gbase + (q0 + r) * NDH + blk * 8);
    }

    auto load_kv = [&](int t) {
        const uint32_t s0 = sb + QARR + (t % 3) * KVSTG;
        const int gk = gbase + (t << 6) * NDH;
#pragma unroll
        for (int i = 0; i < 2; ++i) {
            int c = tid + i * 256;
            int r = c >> 3, blk = c & 7;
            const uint32_t dst = s0 + r * QROWB + blk * 16;
            const int src = gk + r * NDH + blk * 8;
            cp_async16(dst,         kh + src);
            cp_async16(dst + KARRA, vh + src);
        }
        cp_commit();
    };

    load_kv(0);
    if (ntiles > 1) load_kv(1);
    __syncthreads();   // Q smem ready

    uint32_t qf[4][4];
    {
        const uint32_t qa = sb + (wid * 16 + (lane & 15)) * QROWB + (lane >> 4) * 16;
#pragma unroll
        for (int ks = 0; ks < 4; ++ks)
            ldsm_x4(qa + ks * 32, qf[ks][0], qf[ks][1], qf[ks][2], qf[ks][3]);
    }

    float m0r = -1e30f, m1r = -1e30f, lsum0 = 0.0f, lsum1 = 0.0f;
    float o[8][4];
#pragma unroll
    for (int di = 0; di < 8; ++di)
#pragma unroll
        for (int q = 0; q < 4; ++q) o[di][q] = 0.0f;

    for (int t = 0; t < ntiles; ++t) {
        if (t + 1 < ntiles) asm volatile("cp.async.wait_group 1;" ::: "memory");
        else                asm volatile("cp.async.wait_group 0;" ::: "memory");
        __syncthreads();   // readers of stage (t-1)%3 have all finished
        if (t + 2 < ntiles) load_kv(t + 2);   // safe: writes stage (t-1)%3

        const uint32_t kbase = sb + QARR + (t % 3) * KVSTG;

        // ---- S = Q K^T ----
        float s[8][4];
#pragma unroll
        for (int ni = 0; ni < 8; ++ni)
#pragma unroll
            for (int q = 0; q < 4; ++q) s[ni][q] = 0.0f;

#pragma unroll
        for (int ks = 0; ks < 4; ++ks) {
#pragma unroll
            for (int nb = 0; nb < 4; ++nb) {
                const uint32_t adr = kbase
                    + (nb * 16 + (lane & 7) + 8 * (lane >> 4)) * QROWB
                    + ((lane >> 3) & 1) * 16 + ks * 32;
                uint32_t t0, t1, t2, t3;
                ldsm_x4(adr, t0, t1, t2, t3);
                uint32_t bh0[2] = {t0, t1}, bh1[2] = {t2, t3};
                mma16816(s[nb*2],   qf[ks], bh0);
                mma16816(s[nb*2+1], qf[ks], bh1);
            }
        }

        // ---- mask (last tile only) + online softmax (log2 domain) ----
        if (t == ntiles - 1) {
            const int cb = (t << 6) + 2 * (lane & 3);
#pragma unroll
            for (int ni = 0; ni < 8; ++ni) {
                const int c0 = cb + 8 * ni;
                if (c0     >= len) { s[ni][0] = -1e30f; s[ni][2] = -1e30f; }
                if (c0 + 1 >= len) { s[ni][1] = -1e30f; s[ni][3] = -1e30f; }
            }
        }
        float tmax0 = -1e30f, tmax1 = -1e30f;
#pragma unroll
        for (int ni = 0; ni < 8; ++ni) {
            tmax0 = fmaxf(tmax0, fmaxf(s[ni][0], s[ni][1]));
            tmax1 = fmaxf(tmax1, fmaxf(s[ni][2], s[ni][3]));
        }
        tmax0 = fmaxf(tmax0, __shfl_xor_sync(0xffffffffu, tmax0, 1));
        tmax0 = fmaxf(tmax0, __shfl_xor_sync(0xffffffffu, tmax0, 2));
        tmax1 = fmaxf(tmax1, __shfl_xor_sync(0xffffffffu, tmax1, 1));
        tmax1 = fmaxf(tmax1, __shfl_xor_sync(0xffffffffu, tmax1, 2));

        const float mn0 = fmaxf(m0r, tmax0);
        const float mn1 = fmaxf(m1r, tmax1);
        const float sc0 = ex2(m0r - mn0);
        const float sc1 = ex2(m1r - mn1);
        m0r = mn0; m1r = mn1;

        float ps0 = 0.0f, ps1 = 0.0f;
#pragma unroll
        for (int ni = 0; ni < 8; ++ni) {
            float p0 = ex2(s[ni][0] - mn0);
            float p1 = ex2(s[ni][1] - mn0);
            float p2 = ex2(s[ni][2] - mn1);
            float p3 = ex2(s[ni][3] - mn1);
            ps0 += p0 + p1;
            ps1 += p2 + p3;
            s[ni][0] = __uint_as_float(pack_h2(p0, p1));
            s[ni][2] = __uint_as_float(pack_h2(p2, p3));
        }
        ps0 += __shfl_xor_sync(0xffffffffu, ps0, 1);
        ps0 += __shfl_xor_sync(0xffffffffu, ps0, 2);
        ps1 += __shfl_xor_sync(0xffffffffu, ps1, 1);
        ps1 += __shfl_xor_sync(0xffffffffu, ps1, 2);
        lsum0 = lsum0 * sc0 + ps0;
        lsum1 = lsum1 * sc1 + ps1;
#pragma unroll
        for (int di = 0; di < 8; ++di) {
            o[di][0] *= sc0; o[di][1] *= sc0;
            o[di][2] *= sc1; o[di][3] *= sc1;
        }

        // ---- O += P V ----
        const uint32_t vbase = kbase + KARRA;
#pragma unroll
        for (int ks2 = 0; ks2 < 4; ++ks2) {
            uint32_t Ahf[4] = {
                __float_as_uint(s[2*ks2][0]),   __float_as_uint(s[2*ks2][2]),
                __float_as_uint(s[2*ks2+1][0]), __float_as_uint(s[2*ks2+1][2]) };
#pragma unroll
            for (int db = 0; db < 4; ++db) {
                const uint32_t adr = vbase
                    + (ks2 * 16 + (lane & 7) + 8 * ((lane >> 3) & 1)) * QROWB
                    + ((lane >> 4) & 1) * 16 + db * 32;
                uint32_t t0, t1, t2, t3;
                ldsm_x4_t(adr, t0, t1, t2, t3);
                uint32_t vh0[2] = {t0, t1}, vh1[2] = {t2, t3};
                mma16816(o[db*2],   Ahf, vh0);
                mma16816(o[db*2+1], Ahf, vh1);
            }
        }
        // no trailing barrier: next iteration's leading barrier orders these
        // reads before any prefetch issued after it overwrites this stage.
    }

    // ---- normalize + write ctx hi [B,S,D] ----
    const float inv0 = 1.0f / lsum0;
    const float inv1 = 1.0f / lsum1;
    const int r  = lane >> 2;
    const int dc = 2 * (lane & 3);
    const int qrow0 = q0 + wid * 16 + r;
#pragma unroll
    for (int di = 0; di < 8; ++di) {
        const int d = 8 * di + dc;
        *(uint32_t*)&ch[((b * NS + qrow0) * ND) + h * NDH + d] =
            pack_h2(o[di][0] * inv0, o[di][1] * inv0);
        *(uint32_t*)&ch[((b * NS + qrow0 + 8) * ND) + h * NDH + d] =
            pack_h2(o[di][2] * inv1, o[di][3] * inv1);
    }
}

// ---------------------------------------------------------------------------
extern "C" void kernel_launch(void* const* d_in, const int* in_sizes, int n_in,
                              void* d_out, int out_size)
{
    (void)in_sizes; (void)n_in; (void)out_size;
    const float* Q  = (const float*)d_in[0];
    const float* K  = (const float*)d_in[1];
    const float* V  = (const float*)d_in[2];
    const float* Wq = (const float*)d_in[3];
    const float* bq = (const float*)d_in[4];
    const float* Wk = (const float*)d_in[5];
    const float* bk = (const float*)d_in[6];
    const float* Wv = (const float*)d_in[7];
    const float* bv = (const float*)d_in[8];
    const float* Wo = (const float*)d_in[9];
    const float* bo = (const float*)d_in[10];
    const void*  mk = d_in[11];
    float* out = (float*)d_out;

    __half *pqh, *pkh, *pvh, *pch, *pah, *pwh;
    cudaGetSymbolAddress((void**)&pqh, g_qh);
    cudaGetSymbolAddress((void**)&pkh, g_kh);
    cudaGetSymbolAddress((void**)&pvh, g_vh);
    cudaGetSymbolAddress((void**)&pch, g_ch);
    cudaGetSymbolAddress((void**)&pah, g_ah);
    cudaGetSymbolAddress((void**)&pwh, g_wh);

    const int NACT = NB * NS * ND;   // 4194304
    const int NW   = ND * ND;        // 262144
    const int nx4 = NACT / 4;
    const int nw4 = NW / 4;

    cudaFuncSetAttribute((const void*)proj_qkv,
                         cudaFuncAttributeMaxDynamicSharedMemorySize, PROJ_SMEM);
    cudaFuncSetAttribute((const void*)proj_o,
                         cudaFuncAttributeMaxDynamicSharedMemorySize, PROJ_SMEM);
    cudaFuncSetAttribute((const void*)attn_hmma,
                         cudaFuncAttributeMaxDynamicSharedMemorySize, ATTN_SMEM);

    const float QSCALE = 0.125f * 1.4426950408889634f;  // 1/sqrt(64) * log2(e)

    // 1) weight hi conversions (4 in one launch)
    conv_w4<<<dim3((nw4 / 2 + 255) / 256, 4), 256>>>(
        Wq, Wk, Wv, Wo, pwh, pwh + NW, pwh + 2 * NW, pwh + 3 * NW, nw4);
    // 2) activation hi conversions (3 in one launch)
    conv_a3<<<dim3((nx4 / 2 + 255) / 256, 3), 256>>>(
        Q, K, V, pah, pah + NACT, pah + 2 * NACT, nx4);
    // 3) fused Q/K/V projections (persistent z-loop, single wave)
    proj_qkv<<<dim3(64, 4), 256, PROJ_SMEM>>>(
        pah,            pwh,          bq, pqh, QSCALE,
        pah + NACT,     pwh + NW,     bk, pkh,
        pah + 2 * NACT, pwh + 2 * NW, bv, pvh);
    // 4) attention
    attn_hmma<<<dim3(NS / 128, NB * NH), 256, ATTN_SMEM>>>(
        pqh, pkh, pvh, pch, mk);
    // 5) output projection
    proj_o<<<dim3(64, 4), 256, PROJ_SMEM>>>(
        pch, pwh + 3 * NW, bo, out);
}